// round 4
// baseline (speedup 1.0000x reference)
#include <cuda_runtime.h>
#include <cuda_bf16.h>
#include <cstdint>

// Problem constants (fixed by the dataset)
#define B_DIM   16
#define N_DIM   50000
#define E_DIM   1600000
#define CLAMP_MIN_F (-10.0f)
#define CLAMP_MAX_F ( 10.0f)
#define EPS_F   (1e-6f)

#define QSTEPS  252.0f
#define INV_Q   (1.0f / 252.0f)

// Transposed (N, B) scratch: each node's 16 batch values are contiguous (64B).
__device__ float   g_ET [N_DIM * B_DIM];   // E transposed (exact, for fallback)
__device__ float   g_OT [N_DIM * B_DIM];   // o_pre transposed
__device__ float   g_ACC[N_DIM * B_DIM];   // accumulator, init to E + chem
__device__ uint8_t g_CE [N_DIM * B_DIM];   // quantized E codes (sign screening)

// code: 0   -> E <= 0        => sign +1 always (Oj >= 0 >= En)
//       255 -> E >= 1        => sign -1 always (Oj < 1 <= En)
//       c in [1,252]: En in ~[(c-1)/252, c/252]
__device__ __forceinline__ uint8_t quant_code(float e)
{
    if (e <= 0.0f) return 0;
    if (e >= 1.0f) return 255;
    int k = (int)floorf(e * QSTEPS);        // 0..251
    return (uint8_t)(k + 1);                // 1..252
}

// ---------------------------------------------------------------------------
// Kernel A: transpose + init accumulator + quant codes, q-split node-major.
// tid = q*N + n : thread handles batches b = 4q..4q+3 of node n.
// ---------------------------------------------------------------------------
__global__ void __launch_bounds__(256)
prep_kernel(const float* __restrict__ chem,
            const float* __restrict__ E,
            const float* __restrict__ o_pre)
{
    int tid = blockIdx.x * blockDim.x + threadIdx.x;
    if (tid >= 4 * N_DIM) return;
    int q = tid / N_DIM;          // 0..3 (batch quad)
    int n = tid - q * N_DIM;      // node

    float et[4], ot[4], ac[4];
    uint8_t cc[4];
    #pragma unroll
    for (int j = 0; j < 4; j++) {
        int b = q * 4 + j;
        float e = __ldg(&E    [b * N_DIM + n]);
        float o = __ldg(&o_pre[b * N_DIM + n]);
        float c = __ldg(&chem [b * N_DIM + n]);
        et[j] = e;
        ot[j] = o;
        ac[j] = e + c;            // fold chem_influence into accumulator init
        cc[j] = quant_code(e);
    }

    int t = n * B_DIM + q * 4;
    *reinterpret_cast<float4*>(&g_ET [t]) = make_float4(et[0], et[1], et[2], et[3]);
    *reinterpret_cast<float4*>(&g_OT [t]) = make_float4(ot[0], ot[1], ot[2], ot[3]);
    *reinterpret_cast<float4*>(&g_ACC[t]) = make_float4(ac[0], ac[1], ac[2], ac[3]);
    *reinterpret_cast<uint32_t*>(&g_CE[t]) =
        (uint32_t)cc[0] | ((uint32_t)cc[1] << 8) |
        ((uint32_t)cc[2] << 16) | ((uint32_t)cc[3] << 24);
}

// ---------------------------------------------------------------------------
// Sign resolution: definitive from the code when Oj is clearly outside the
// bucket (>= 1-step conservative margin against fp rounding of the quantizer);
// otherwise exact scalar 4B load from g_ET. Bit-exact vs the reference.
// ---------------------------------------------------------------------------
__device__ __forceinline__ float signed_oj(float Oj, uint32_t code,
                                           const float* __restrict__ en_exact)
{
    float oscaled = Oj * QSTEPS;
    float fc = (float)code;
    // +1 definitive: code==0, or Oj >= (c+1)/252  (=> Oj > En guaranteed)
    if (code == 0 || (code != 255 && oscaled >= fc + 1.0f)) return Oj;
    // -1 definitive: code==255, or Oj <= (c-2)/252 (=> Oj < En guaranteed)
    if (code == 255 || oscaled <= fc - 2.0f) return -Oj;
    // ambiguous (~0.4%): exact comparison
    float En = __ldg(en_exact);
    return (Oj >= En) ? Oj : -Oj;
}

// ---------------------------------------------------------------------------
// Kernel B: edge scatter. 4 lanes per edge; each lane owns one batch quad.
// Per lane: 64B-block-contiguous Oj float4 gather, 4B code-word gather,
// rare scalar En fallback, one RED.128 (no-return L2-side add).
// En gather traffic: 102MB -> ~29MB.
// ---------------------------------------------------------------------------
__global__ void __launch_bounds__(256)
edge_kernel(const float* __restrict__ w,
            const int*   __restrict__ src,
            const int*   __restrict__ dst)
{
    int t = blockIdx.x * blockDim.x + threadIdx.x;
    if (t >= E_DIM * 4) return;
    int e = t >> 2;
    int q = t & 3;

    int   s  = __ldg(&src[e]);
    int   d  = __ldg(&dst[e]);
    float wv = __ldg(&w[e]);

    const int ob = s * B_DIM + q * 4;     // Oj block offset
    const int db = d * B_DIM + q * 4;     // dst block offset

    const float4   Oj = __ldg(reinterpret_cast<const float4*>(&g_OT[ob]));
    const uint32_t cw = *reinterpret_cast<const uint32_t*>(&g_CE[db]);

    float4 c;
    c.x = signed_oj(Oj.x, (cw      ) & 0xFF, &g_ET[db + 0]) * wv;
    c.y = signed_oj(Oj.y, (cw >>  8) & 0xFF, &g_ET[db + 1]) * wv;
    c.z = signed_oj(Oj.z, (cw >> 16) & 0xFF, &g_ET[db + 2]) * wv;
    c.w = signed_oj(Oj.w, (cw >> 24)       , &g_ET[db + 3]) * wv;

    float* p = &g_ACC[db];
    asm volatile("red.global.add.v4.f32 [%0], {%1, %2, %3, %4};"
                 :: "l"(p), "f"(c.x), "f"(c.y), "f"(c.z), "f"(c.w)
                 : "memory");
}

// ---------------------------------------------------------------------------
// Kernel C: epilogue, q-split node-major (tid = q*N + n).
// ---------------------------------------------------------------------------
__global__ void __launch_bounds__(256)
final_kernel(const float* __restrict__ E,
             const float* __restrict__ threshold,
             const float* __restrict__ decay,
             float* __restrict__ out)
{
    int tid = blockIdx.x * blockDim.x + threadIdx.x;
    if (tid >= 4 * N_DIM) return;
    int q = tid / N_DIM;
    int n = tid - q * N_DIM;

    float4 Sv  = *reinterpret_cast<const float4*>(&g_ACC[n * B_DIM + q * 4]);
    float  thr = __ldg(&threshold[n]);
    float  dec = __ldg(&decay[n]);

    float Sa[4] = {Sv.x, Sv.y, Sv.z, Sv.w};
    #pragma unroll
    for (int j = 0; j < 4; j++) {
        int b = q * 4 + j;
        float S  = fminf(fmaxf(Sa[j], CLAMP_MIN_F), CLAMP_MAX_F);
        float Ev = __ldg(&E[b * N_DIM + n]);

        bool  gt    = S > thr;
        float new_o = fmaxf(S - thr, 0.0f);
        bool  mask  = (!gt) && (fabsf(S - Ev) <= EPS_F);
        float new_e = gt ? new_o : (mask ? (Ev - dec) : S);

        out[b * N_DIM + n]                 = new_o;
        out[B_DIM * N_DIM + b * N_DIM + n] = new_e;
    }
}

// ---------------------------------------------------------------------------
// Launch. Inputs (metadata order):
//   0 chem_influence (B,N) f32   1 E (B,N) f32       2 o_pre (B,N) f32
//   3 w (E,) f32                 4 threshold (N,) f32 5 decay (N,) f32
//   6 src (E,) i32               7 dst (E,) i32
// Output: new_o (B,N) then new_e (B,N) concatenated, f32.
// ---------------------------------------------------------------------------
extern "C" void kernel_launch(void* const* d_in, const int* in_sizes, int n_in,
                              void* d_out, int out_size)
{
    const float* chem  = (const float*)d_in[0];
    const float* E     = (const float*)d_in[1];
    const float* o_pre = (const float*)d_in[2];
    const float* w     = (const float*)d_in[3];
    const float* thr   = (const float*)d_in[4];
    const float* dec   = (const float*)d_in[5];
    const int*   src   = (const int*)  d_in[6];
    const int*   dst   = (const int*)  d_in[7];
    float* out = (float*)d_out;

    const int THREADS = 256;
    int qn_blocks   = (4 * N_DIM + THREADS - 1) / THREADS;
    int edge_blocks = (E_DIM * 4 + THREADS - 1) / THREADS;

    prep_kernel <<<qn_blocks,   THREADS>>>(chem, E, o_pre);
    edge_kernel <<<edge_blocks, THREADS>>>(w, src, dst);
    final_kernel<<<qn_blocks,   THREADS>>>(E, thr, dec, out);
}

// round 5
// speedup vs baseline: 1.1000x; 1.1000x over previous
#include <cuda_runtime.h>
#include <cuda_bf16.h>
#include <cstdint>

// Problem constants (fixed by the dataset)
#define B_DIM   16
#define N_DIM   50000          // divisible by 4
#define N4_DIM  (N_DIM / 4)    // 12500
#define E_DIM   1600000
#define CLAMP_MIN_F (-10.0f)
#define CLAMP_MAX_F ( 10.0f)
#define EPS_F   (1e-6f)

// Transposed (N, B) scratch: each node's 16 batch values are contiguous (64B).
// 3 x 3.2MB = 9.6MB -> fully L2-resident.
__device__ float g_ET [N_DIM * B_DIM];   // E transposed
__device__ float g_OT [N_DIM * B_DIM];   // o_pre transposed
__device__ float g_ACC[N_DIM * B_DIM];   // accumulator, init to E + chem

// ---------------------------------------------------------------------------
// Kernel A: transpose + init accumulator. Fat threads:
// tid = q*N4 + n4 handles batch quad q (batches 4q..4q+3) x node quad
// (nodes 4*n4..4*n4+3). 12 independent LDG.128 (coalesced: consecutive
// threads read consecutive 16B of each row) -> high MLP; register 4x4
// transpose; 12 STG.128 (full 32B sectors, 64B node blocks).
// ---------------------------------------------------------------------------
__global__ void __launch_bounds__(256)
prep_kernel(const float* __restrict__ chem,
            const float* __restrict__ E,
            const float* __restrict__ o_pre)
{
    int tid = blockIdx.x * blockDim.x + threadIdx.x;
    if (tid >= 4 * N4_DIM) return;
    int q  = tid / N4_DIM;        // 0..3 (batch quad)
    int n4 = tid - q * N4_DIM;    // node quad index
    int n0 = n4 * 4;              // first node

    float4 ev[4], ov[4], cv[4];
    #pragma unroll
    for (int j = 0; j < 4; j++) {
        int b = q * 4 + j;
        ev[j] = __ldg(reinterpret_cast<const float4*>(&E    [b * N_DIM + n0]));
        ov[j] = __ldg(reinterpret_cast<const float4*>(&o_pre[b * N_DIM + n0]));
        cv[j] = __ldg(reinterpret_cast<const float4*>(&chem [b * N_DIM + n0]));
    }

    // 4x4 register transpose: node i gets component i of each batch-j vector.
    #pragma unroll
    for (int i = 0; i < 4; i++) {
        float e0 = (i==0)?ev[0].x:(i==1)?ev[0].y:(i==2)?ev[0].z:ev[0].w;
        float e1 = (i==0)?ev[1].x:(i==1)?ev[1].y:(i==2)?ev[1].z:ev[1].w;
        float e2 = (i==0)?ev[2].x:(i==1)?ev[2].y:(i==2)?ev[2].z:ev[2].w;
        float e3 = (i==0)?ev[3].x:(i==1)?ev[3].y:(i==2)?ev[3].z:ev[3].w;
        float o0 = (i==0)?ov[0].x:(i==1)?ov[0].y:(i==2)?ov[0].z:ov[0].w;
        float o1 = (i==0)?ov[1].x:(i==1)?ov[1].y:(i==2)?ov[1].z:ov[1].w;
        float o2 = (i==0)?ov[2].x:(i==1)?ov[2].y:(i==2)?ov[2].z:ov[2].w;
        float o3 = (i==0)?ov[3].x:(i==1)?ov[3].y:(i==2)?ov[3].z:ov[3].w;
        float c0 = (i==0)?cv[0].x:(i==1)?cv[0].y:(i==2)?cv[0].z:cv[0].w;
        float c1 = (i==0)?cv[1].x:(i==1)?cv[1].y:(i==2)?cv[1].z:cv[1].w;
        float c2 = (i==0)?cv[2].x:(i==1)?cv[2].y:(i==2)?cv[2].z:cv[2].w;
        float c3 = (i==0)?cv[3].x:(i==1)?cv[3].y:(i==2)?cv[3].z:cv[3].w;

        int t = (n0 + i) * B_DIM + q * 4;
        *reinterpret_cast<float4*>(&g_ET [t]) = make_float4(e0, e1, e2, e3);
        *reinterpret_cast<float4*>(&g_OT [t]) = make_float4(o0, o1, o2, o3);
        *reinterpret_cast<float4*>(&g_ACC[t]) = make_float4(e0 + c0, e1 + c1,
                                                            e2 + c2, e3 + c3);
    }
}

// ---------------------------------------------------------------------------
// Kernel B: edge scatter (unchanged from R3 — at its LTS roofline).
// 4 lanes per edge; each lane owns one batch quad (float4). Quad lanes load
// contiguous 16B pieces of the edge's 64B block. red.global.add.v4.f32 ->
// no-return L2-side add, one RED.128 per lane.
// ---------------------------------------------------------------------------
__global__ void __launch_bounds__(256)
edge_kernel(const float* __restrict__ w,
            const int*   __restrict__ src,
            const int*   __restrict__ dst)
{
    int t = blockIdx.x * blockDim.x + threadIdx.x;
    if (t >= E_DIM * 4) return;
    int e = t >> 2;
    int q = t & 3;

    int   s  = __ldg(&src[e]);
    int   d  = __ldg(&dst[e]);
    float wv = __ldg(&w[e]);

    const float4 Oj = __ldg(reinterpret_cast<const float4*>(&g_OT[s * B_DIM + q * 4]));
    const float4 En = __ldg(reinterpret_cast<const float4*>(&g_ET[d * B_DIM + q * 4]));

    float4 c;
    c.x = (Oj.x >= En.x) ? (Oj.x * wv) : (-Oj.x * wv);
    c.y = (Oj.y >= En.y) ? (Oj.y * wv) : (-Oj.y * wv);
    c.z = (Oj.z >= En.z) ? (Oj.z * wv) : (-Oj.z * wv);
    c.w = (Oj.w >= En.w) ? (Oj.w * wv) : (-Oj.w * wv);

    float* p = &g_ACC[d * B_DIM + q * 4];
    asm volatile("red.global.add.v4.f32 [%0], {%1, %2, %3, %4};"
                 :: "l"(p), "f"(c.x), "f"(c.y), "f"(c.z), "f"(c.w)
                 : "memory");
}

// ---------------------------------------------------------------------------
// Kernel C: epilogue, fat threads: tid = q*N4 + n4 handles 4 batches x 4
// nodes. 4 ACC LDG.128 (L2 hit) + 4 E LDG.128 + thr/dec LDG.128, 8 coalesced
// STG.128 outputs.
// ---------------------------------------------------------------------------
__global__ void __launch_bounds__(256)
final_kernel(const float* __restrict__ E,
             const float* __restrict__ threshold,
             const float* __restrict__ decay,
             float* __restrict__ out)
{
    int tid = blockIdx.x * blockDim.x + threadIdx.x;
    if (tid >= 4 * N4_DIM) return;
    int q  = tid / N4_DIM;
    int n4 = tid - q * N4_DIM;
    int n0 = n4 * 4;

    // acc[i] = batches (q*4..q*4+3) of node n0+i
    float4 acc[4], Ev[4];
    #pragma unroll
    for (int i = 0; i < 4; i++)
        acc[i] = *reinterpret_cast<const float4*>(&g_ACC[(n0 + i) * B_DIM + q * 4]);
    #pragma unroll
    for (int j = 0; j < 4; j++)
        Ev[j] = __ldg(reinterpret_cast<const float4*>(&E[(q * 4 + j) * N_DIM + n0]));

    float4 thr = __ldg(reinterpret_cast<const float4*>(&threshold[n0]));
    float4 dec = __ldg(reinterpret_cast<const float4*>(&decay[n0]));
    float thra[4] = {thr.x, thr.y, thr.z, thr.w};
    float deca[4] = {dec.x, dec.y, dec.z, dec.w};

    #pragma unroll
    for (int j = 0; j < 4; j++) {            // batch b = q*4+j
        int b = q * 4 + j;
        float4 no, ne;
        float* nop = &no.x;
        float* nep = &ne.x;
        float  eva[4] = {Ev[j].x, Ev[j].y, Ev[j].z, Ev[j].w};
        #pragma unroll
        for (int i = 0; i < 4; i++) {        // node n0+i
            float S = (j==0) ? ((i==0)?acc[0].x:(i==1)?acc[1].x:(i==2)?acc[2].x:acc[3].x)
                    : (j==1) ? ((i==0)?acc[0].y:(i==1)?acc[1].y:(i==2)?acc[2].y:acc[3].y)
                    : (j==2) ? ((i==0)?acc[0].z:(i==1)?acc[1].z:(i==2)?acc[2].z:acc[3].z)
                             : ((i==0)?acc[0].w:(i==1)?acc[1].w:(i==2)?acc[2].w:acc[3].w);
            S = fminf(fmaxf(S, CLAMP_MIN_F), CLAMP_MAX_F);
            float ev = eva[i];
            bool  gt    = S > thra[i];
            float new_o = fmaxf(S - thra[i], 0.0f);
            bool  mask  = (!gt) && (fabsf(S - ev) <= EPS_F);
            float new_e = gt ? new_o : (mask ? (ev - deca[i]) : S);
            nop[i] = new_o;
            nep[i] = new_e;
        }
        *reinterpret_cast<float4*>(&out[b * N_DIM + n0])                 = no;
        *reinterpret_cast<float4*>(&out[B_DIM * N_DIM + b * N_DIM + n0]) = ne;
    }
}

// ---------------------------------------------------------------------------
// Launch. Inputs (metadata order):
//   0 chem_influence (B,N) f32   1 E (B,N) f32       2 o_pre (B,N) f32
//   3 w (E,) f32                 4 threshold (N,) f32 5 decay (N,) f32
//   6 src (E,) i32               7 dst (E,) i32
// Output: new_o (B,N) then new_e (B,N) concatenated, f32.
// ---------------------------------------------------------------------------
extern "C" void kernel_launch(void* const* d_in, const int* in_sizes, int n_in,
                              void* d_out, int out_size)
{
    const float* chem  = (const float*)d_in[0];
    const float* E     = (const float*)d_in[1];
    const float* o_pre = (const float*)d_in[2];
    const float* w     = (const float*)d_in[3];
    const float* thr   = (const float*)d_in[4];
    const float* dec   = (const float*)d_in[5];
    const int*   src   = (const int*)  d_in[6];
    const int*   dst   = (const int*)  d_in[7];
    float* out = (float*)d_out;

    const int THREADS = 256;
    int fat_blocks  = (4 * N4_DIM + THREADS - 1) / THREADS;   // 196
    int edge_blocks = (E_DIM * 4 + THREADS - 1) / THREADS;

    prep_kernel <<<fat_blocks,  THREADS>>>(chem, E, o_pre);
    edge_kernel <<<edge_blocks, THREADS>>>(w, src, dst);
    final_kernel<<<fat_blocks,  THREADS>>>(E, thr, dec, out);
}